// round 2
// baseline (speedup 1.0000x reference)
#include <cuda_runtime.h>

// OU Euler-Maruyama: x_{t+1} = a*x_t + b_t,  a = 1 - gamma*dt (const per chain),
// b_t = gamma*mu*dt + sigma*sqrt(dt)*eps_t.
// One warp per (n,m) chain. Each tile = 128 timesteps: lane L holds float4
// covering t = tile*128 + 4L .. +3 (coalesced). Constant-coefficient affine
// warp scan: 5 shuffle steps with weights a^4,a^8,a^16,a^32,a^64.
// 4-deep register prefetch ring to keep ~2KB/warp of HBM loads in flight.

#define T_STEPS 20000
#define NV4     5000            // T_STEPS / 4 float4s per chain
#define TILES   157             // ceil(5000 / 32)
#define N_CHAIN 2048            // 32 * 64
#define PF      4               // prefetch depth (tiles)

__device__ __forceinline__ float4 load_tile(const float4* __restrict__ np,
                                            int tile, int lane) {
    int idx = tile * 32 + lane;
    if (idx < NV4) return np[idx];
    return make_float4(0.f, 0.f, 0.f, 0.f);
}

__global__ __launch_bounds__(128)
void oup_kernel(const float* __restrict__ theta,
                const float* __restrict__ noise,
                float*       __restrict__ out)
{
    const int warp = (blockIdx.x * blockDim.x + threadIdx.x) >> 5;
    const int lane = threadIdx.x & 31;
    if (warp >= N_CHAIN) return;

    const int n = warp >> 6;                 // chain-param row (m = warp & 63 implicit)
    const float gamma = theta[n * 4 + 0];
    const float mu    = theta[n * 4 + 1];
    const float sigma = theta[n * 4 + 2];
    float x           = theta[n * 4 + 3];    // running state (carry)

    const float a   = 1.0f - gamma * 0.01f;  // dt = 0.01
    const float c0  = gamma * mu * 0.01f;
    const float ssd = sigma * 0.1f;          // sqrt(dt) = 0.1

    // Powers of a for the scan
    const float a2   = a * a;
    const float a4   = a2 * a2;
    const float a8   = a4 * a4;
    const float a16  = a8 * a8;
    const float a32  = a16 * a16;
    const float a64  = a32 * a32;
    const float a128 = a64 * a64;

    // a^(4*lane): exclusive-prefix coefficient for this lane's starting state
    float alane = 1.0f;
    if (lane & 1)  alane *= a4;
    if (lane & 2)  alane *= a8;
    if (lane & 4)  alane *= a16;
    if (lane & 8)  alane *= a32;
    if (lane & 16) alane *= a64;

    const float4* __restrict__ np = (const float4*)(noise + (size_t)warp * T_STEPS);
    float4*       __restrict__ op = (float4*)(out + (size_t)warp * T_STEPS);

    // Prefetch ring
    float4 buf[PF];
#pragma unroll
    for (int k = 0; k < PF; ++k) buf[k] = load_tile(np, k, lane);

    // Process one 128-step tile held in v; returns via updated x (carry).
    auto process = [&](float4 v, int tile) {
        const float b0 = fmaf(ssd, v.x, c0);
        const float b1 = fmaf(ssd, v.y, c0);
        const float b2 = fmaf(ssd, v.z, c0);
        const float b3 = fmaf(ssd, v.w, c0);

        // Thread-local aggregate offset over 4 steps (coefficient = a^4)
        float B = b0;
        B = fmaf(a, B, b1);
        B = fmaf(a, B, b2);
        B = fmaf(a, B, b3);

        // Warp inclusive scan of offsets (Hillis-Steele, weights a^(4*2^s))
        float t;
        t = __shfl_up_sync(0xFFFFFFFFu, B, 1);  if (lane >= 1)  B = fmaf(a4,  t, B);
        t = __shfl_up_sync(0xFFFFFFFFu, B, 2);  if (lane >= 2)  B = fmaf(a8,  t, B);
        t = __shfl_up_sync(0xFFFFFFFFu, B, 4);  if (lane >= 4)  B = fmaf(a16, t, B);
        t = __shfl_up_sync(0xFFFFFFFFu, B, 8);  if (lane >= 8)  B = fmaf(a32, t, B);
        t = __shfl_up_sync(0xFFFFFFFFu, B, 16); if (lane >= 16) B = fmaf(a64, t, B);

        float Bexcl = __shfl_up_sync(0xFFFFFFFFu, B, 1);
        if (lane == 0) Bexcl = 0.0f;
        const float Btop = __shfl_sync(0xFFFFFFFFu, B, 31);

        // State entering this lane's 4 steps
        const float xs = fmaf(alane, x, Bexcl);
        const float y0 = fmaf(a, xs, b0);
        const float y1 = fmaf(a, y0, b1);
        const float y2 = fmaf(a, y1, b2);
        const float y3 = fmaf(a, y2, b3);

        const int idx = tile * 32 + lane;
        if (idx < NV4) op[idx] = make_float4(y0, y1, y2, y3);

        // Advance carry by 128 steps (uniform across warp)
        x = fmaf(a128, x, Btop);
    };

    // 39 macro-iterations of PF tiles (156 tiles), then 1 tail tile (partial)
    for (int mi = 0; mi < (TILES - 1) / PF; ++mi) {
#pragma unroll
        for (int k = 0; k < PF; ++k) {
            const int i = mi * PF + k;
            float4 v = buf[k];
            buf[k] = load_tile(np, i + PF, lane);   // refill (guarded OOB -> 0)
            process(v, i);
        }
    }
    process(buf[0], TILES - 1);   // tile 156: only lanes 0..7 valid (guarded)
}

extern "C" void kernel_launch(void* const* d_in, const int* in_sizes, int n_in,
                              void* d_out, int out_size)
{
    const float* theta = (const float*)d_in[0];   // [32,4]
    const float* noise = (const float*)d_in[1];   // [32,64,20000]
    float* out = (float*)d_out;                   // [32,64,20000]
    (void)in_sizes; (void)n_in; (void)out_size;
    oup_kernel<<<N_CHAIN / 4, 128>>>(theta, noise, out);
}

// round 4
// speedup vs baseline: 1.1815x; 1.1815x over previous
#include <cuda_runtime.h>

// OU Euler-Maruyama: x_{t+1} = a*x_t + b_t,  a = 1 - gamma*dt (const per chain),
// b_t = gamma*mu*dt + sigma*sqrt(dt)*eps_t.
// One warp per (n,m) chain. Tile = 128 timesteps: lane L holds float4 covering
// t = tile*128 + 4L..+3 (coalesced LDG.128/STG.128). Constant-coefficient
// affine warp scan (5 shuffle steps, weights a^4..a^64).
// PF=8 register prefetch ring: 4KB/warp of HBM loads in flight (~56KB/SM),
// 2x the ~27KB needed to cover ~900cyc loaded DRAM latency at 30B/cyc/SM.

#define T_STEPS 20000
#define NV4     5000            // T_STEPS / 4 float4s per chain
#define TILES   157             // ceil(5000 / 32)
#define MACRO   20              // ceil(TILES / PF) -> 160 guarded tiles
#define N_CHAIN 2048            // 32 * 64
#define PF      8               // prefetch depth (tiles)

__device__ __forceinline__ float4 load_tile(const float4* __restrict__ np,
                                            int tile, int lane) {
    int idx = tile * 32 + lane;
    if (idx < NV4) return np[idx];
    return make_float4(0.f, 0.f, 0.f, 0.f);
}

__global__ __launch_bounds__(128)
void oup_kernel(const float* __restrict__ theta,
                const float* __restrict__ noise,
                float*       __restrict__ out)
{
    const int warp = (blockIdx.x * blockDim.x + threadIdx.x) >> 5;
    const int lane = threadIdx.x & 31;
    if (warp >= N_CHAIN) return;

    const int n = warp >> 6;                 // chain-param row (m = warp & 63)
    const float gamma = theta[n * 4 + 0];
    const float mu    = theta[n * 4 + 1];
    const float sigma = theta[n * 4 + 2];
    float x           = theta[n * 4 + 3];    // running state (carry)

    const float a   = 1.0f - gamma * 0.01f;  // dt = 0.01
    const float c0  = gamma * mu * 0.01f;
    const float ssd = sigma * 0.1f;          // sqrt(dt) = 0.1

    const float a2   = a * a;
    const float a4   = a2 * a2;
    const float a8   = a4 * a4;
    const float a16  = a8 * a8;
    const float a32  = a16 * a16;
    const float a64  = a32 * a32;
    const float a128 = a64 * a64;

    // a^(4*lane): exclusive-prefix coefficient for this lane's starting state
    float alane = 1.0f;
    if (lane & 1)  alane *= a4;
    if (lane & 2)  alane *= a8;
    if (lane & 4)  alane *= a16;
    if (lane & 8)  alane *= a32;
    if (lane & 16) alane *= a64;

    const float4* __restrict__ np = (const float4*)(noise + (size_t)warp * T_STEPS);
    float4*       __restrict__ op = (float4*)(out + (size_t)warp * T_STEPS);

    // Prefetch ring
    float4 buf[PF];
#pragma unroll
    for (int k = 0; k < PF; ++k) buf[k] = load_tile(np, k, lane);

    // Process one 128-step tile held in v (OOB-safe: stores predicated; carry
    // corruption past the last real tile is never observed).
    auto process = [&](float4 v, int tile) {
        const float b0 = fmaf(ssd, v.x, c0);
        const float b1 = fmaf(ssd, v.y, c0);
        const float b2 = fmaf(ssd, v.z, c0);
        const float b3 = fmaf(ssd, v.w, c0);

        // Thread-local aggregate offset over 4 steps (coefficient a^4)
        float B = b0;
        B = fmaf(a, B, b1);
        B = fmaf(a, B, b2);
        B = fmaf(a, B, b3);

        // Warp inclusive affine scan (Hillis-Steele, weights a^(4*2^s))
        float t;
        t = __shfl_up_sync(0xFFFFFFFFu, B, 1);  if (lane >= 1)  B = fmaf(a4,  t, B);
        t = __shfl_up_sync(0xFFFFFFFFu, B, 2);  if (lane >= 2)  B = fmaf(a8,  t, B);
        t = __shfl_up_sync(0xFFFFFFFFu, B, 4);  if (lane >= 4)  B = fmaf(a16, t, B);
        t = __shfl_up_sync(0xFFFFFFFFu, B, 8);  if (lane >= 8)  B = fmaf(a32, t, B);
        t = __shfl_up_sync(0xFFFFFFFFu, B, 16); if (lane >= 16) B = fmaf(a64, t, B);

        float Bexcl = __shfl_up_sync(0xFFFFFFFFu, B, 1);
        if (lane == 0) Bexcl = 0.0f;
        const float Btop = __shfl_sync(0xFFFFFFFFu, B, 31);

        // State entering this lane's 4 steps
        const float xs = fmaf(alane, x, Bexcl);
        const float y0 = fmaf(a, xs, b0);
        const float y1 = fmaf(a, y0, b1);
        const float y2 = fmaf(a, y1, b2);
        const float y3 = fmaf(a, y2, b3);

        const int idx = tile * 32 + lane;
        if (idx < NV4) op[idx] = make_float4(y0, y1, y2, y3);

        // Advance carry 128 steps (uniform across warp)
        x = fmaf(a128, x, Btop);
    };

    for (int mi = 0; mi < MACRO; ++mi) {
#pragma unroll
        for (int k = 0; k < PF; ++k) {
            const int i = mi * PF + k;
            float4 v = buf[k];
            buf[k] = load_tile(np, i + PF, lane);   // guarded refill (OOB -> 0)
            process(v, i);
        }
    }
}

extern "C" void kernel_launch(void* const* d_in, const int* in_sizes, int n_in,
                              void* d_out, int out_size)
{
    const float* theta = (const float*)d_in[0];   // [32,4]
    const float* noise = (const float*)d_in[1];   // [32,64,20000]
    float* out = (float*)d_out;                   // [32,64,20000]
    (void)in_sizes; (void)n_in; (void)out_size;
    oup_kernel<<<N_CHAIN / 4, 128>>>(theta, noise, out);
}